// round 5
// baseline (speedup 1.0000x reference)
#include <cuda_runtime.h>

// Problem constants (fixed by reference setup_inputs)
#define BB      4
#define NN      100000
#define CC      128
#define RESV    128
#define NPLANES 3

// Scratch: weighted images, 3 * 4 * 128*128 floats = 786 KB (L2-resident)
__device__ float g_wimg[NPLANES * BB * RESV * RESV];

// ---------------------------------------------------------------------------
// Kernel 1: w_img[plane,b,pix] = sum_c img[b,c,pix] * fc_w[c]
// Each thread handles 4 consecutive pixels (float4), loops over 128 channels.
// Reads the 100 MB of triplane data exactly once, fully coalesced.
// ---------------------------------------------------------------------------
__global__ void __launch_bounds__(256) reduce_planes_kernel(
    const float* __restrict__ c_xz,
    const float* __restrict__ c_xy,
    const float* __restrict__ c_yz,
    const float* __restrict__ fc_w)
{
    __shared__ float sw[CC];
    for (int c = threadIdx.x; c < CC; c += blockDim.x)
        sw[c] = fc_w[c];
    __syncthreads();

    const int pix4_per_img = (RESV * RESV) / 4;               // 4096
    const int total = NPLANES * BB * pix4_per_img;            // 49152

    for (int tid = blockIdx.x * blockDim.x + threadIdx.x;
         tid < total; tid += gridDim.x * blockDim.x)
    {
        int img   = tid / pix4_per_img;                       // 0..11
        int pix4  = tid - img * pix4_per_img;
        int plane = img / BB;
        int b     = img - plane * BB;

        const float* src = (plane == 0) ? c_xz : (plane == 1) ? c_xy : c_yz;
        const float4* base = reinterpret_cast<const float4*>(
            src + (size_t)b * CC * RESV * RESV) + pix4;

        float4 acc = make_float4(0.f, 0.f, 0.f, 0.f);
#pragma unroll 8
        for (int c = 0; c < CC; ++c) {
            float  w = sw[c];
            float4 v = __ldg(base + c * pix4_per_img);
            acc.x = fmaf(v.x, w, acc.x);
            acc.y = fmaf(v.y, w, acc.y);
            acc.z = fmaf(v.z, w, acc.z);
            acc.w = fmaf(v.w, w, acc.w);
        }
        reinterpret_cast<float4*>(g_wimg)[tid] = acc;
    }
}

// ---------------------------------------------------------------------------
// Kernel 2: per-point triplane bilinear sample of the weighted images + tail.
// ---------------------------------------------------------------------------
__device__ __forceinline__ float bilerp(const float* __restrict__ img,
                                        float u, float v)
{
    // align_corners=True unnormalize
    float x = u * (float)(RESV - 1);
    float y = v * (float)(RESV - 1);
    float x0f = floorf(x);
    float y0f = floorf(y);
    float wx = x - x0f;
    float wy = y - y0f;
    int x0 = (int)x0f;
    int y0 = (int)y0f;
    // u,v are clamped to [0, 1-1e-5] upstream, so x0 in [0,126]; clamps are
    // belt-and-braces to match the reference exactly.
    int x1 = min(x0 + 1, RESV - 1);
    int y1 = min(y0 + 1, RESV - 1);
    x0 = max(0, min(x0, RESV - 1));
    y0 = max(0, min(y0, RESV - 1));

    float v00 = __ldg(img + y0 * RESV + x0);
    float v01 = __ldg(img + y0 * RESV + x1);
    float v10 = __ldg(img + y1 * RESV + x0);
    float v11 = __ldg(img + y1 * RESV + x1);

    float iwx = 1.f - wx, iwy = 1.f - wy;
    return v00 * iwx * iwy + v01 * wx * iwy + v10 * iwx * wy + v11 * wx * wy;
}

__device__ __forceinline__ float to_uv(float pc)
{
    const float inv = 1.0f / (1.0f + 0.1f + 1e-5f);   // normalize_coordinate
    float u = pc * inv + 0.5f;
    return fminf(fmaxf(u, 0.0f), 1.0f - 1e-5f);
}

__global__ void __launch_bounds__(256) sample_kernel(
    const float* __restrict__ p,
    const float* __restrict__ fc_w,
    const float* __restrict__ fc_b,
    float* __restrict__ out)
{
    const float w0   = __ldg(fc_w + CC + 0);
    const float w1   = __ldg(fc_w + CC + 1);
    const float w2   = __ldg(fc_w + CC + 2);
    const float bias = __ldg(fc_b);

    const int total = BB * NN;
    for (int i = blockIdx.x * blockDim.x + threadIdx.x;
         i < total; i += gridDim.x * blockDim.x)
    {
        int b = i / NN;

        float px = __ldg(p + 3 * i + 0);
        float py = __ldg(p + 3 * i + 1);
        float pz = __ldg(p + 3 * i + 2);

        const float* img_xz = g_wimg + (0 * BB + b) * RESV * RESV;
        const float* img_xy = g_wimg + (1 * BB + b) * RESV * RESV;
        const float* img_yz = g_wimg + (2 * BB + b) * RESV * RESV;

        // plane uv: (ia -> u -> W axis, ib -> v -> H axis)
        float s = bilerp(img_xz, to_uv(px), to_uv(pz));
        s      += bilerp(img_xy, to_uv(px), to_uv(py));
        s      += bilerp(img_yz, to_uv(py), to_uv(pz));

        out[i] = s + px * w0 + py * w1 + pz * w2 + bias;
    }
}

extern "C" void kernel_launch(void* const* d_in, const int* in_sizes, int n_in,
                              void* d_out, int out_size)
{
    const float* p    = (const float*)d_in[0];
    const float* c_xz = (const float*)d_in[1];
    const float* c_xy = (const float*)d_in[2];
    const float* c_yz = (const float*)d_in[3];
    const float* fc_w = (const float*)d_in[4];
    const float* fc_b = (const float*)d_in[5];
    float* out = (float*)d_out;

    // Kernel 1: 3*B*RES*RES/4 = 49152 threads -> 192 blocks of 256
    reduce_planes_kernel<<<192, 256>>>(c_xz, c_xy, c_yz, fc_w);

    // Kernel 2: one thread per (b, n) = 400000
    int total = BB * NN;
    sample_kernel<<<(total + 255) / 256, 256>>>(p, fc_w, fc_b, out);
}

// round 6
// speedup vs baseline: 1.3633x; 1.3633x over previous
#include <cuda_runtime.h>

// Problem constants (fixed by reference setup_inputs)
#define BB      4
#define NN      100000
#define CC      128
#define RESV    128
#define NPLANES 3
#define CHUNKS  4                       // channel chunks of 32
#define PIX4    ((RESV * RESV) / 4)     // 4096 float4 pixels per image
#define NIMG    (NPLANES * BB)          // 12 weighted images

// Scratch. g_part: per-chunk partial weighted images (CHUNKS*12*64KB = 12.6MB).
// g_wimg: final weighted images (786KB, L2/L1-resident for the sample pass).
__device__ float4 g_part[CHUNKS * NIMG * PIX4];
__device__ float  g_wimg[NIMG * RESV * RESV];

// ---------------------------------------------------------------------------
// Kernel 1: partial reduce. Thread -> (chunk, img, pix4); loops 32 channels.
// 4x the thread count of the monolithic version => 4x outstanding DRAM loads.
// ---------------------------------------------------------------------------
__global__ void __launch_bounds__(256) reduce_partial_kernel(
    const float* __restrict__ c_xz,
    const float* __restrict__ c_xy,
    const float* __restrict__ c_yz,
    const float* __restrict__ fc_w)
{
    __shared__ float sw[CC];
    for (int c = threadIdx.x; c < CC; c += blockDim.x)
        sw[c] = fc_w[c];
    __syncthreads();

    const int per_chunk = NIMG * PIX4;               // 49152
    const int total     = CHUNKS * per_chunk;        // 196608

    for (int tid = blockIdx.x * blockDim.x + threadIdx.x;
         tid < total; tid += gridDim.x * blockDim.x)
    {
        int chunk = tid / per_chunk;
        int rest  = tid - chunk * per_chunk;
        int img   = rest / PIX4;                     // 0..11
        int pix4  = rest - img * PIX4;
        int plane = img / BB;
        int b     = img - plane * BB;

        const float* src = (plane == 0) ? c_xz : (plane == 1) ? c_xy : c_yz;
        const float4* base = reinterpret_cast<const float4*>(
            src + (size_t)b * CC * RESV * RESV) + (size_t)chunk * 32 * PIX4 + pix4;

        const float* w = sw + chunk * 32;
        float4 acc = make_float4(0.f, 0.f, 0.f, 0.f);
#pragma unroll 8
        for (int c = 0; c < 32; ++c) {
            float  wc = w[c];
            float4 v  = __ldg(base + c * PIX4);
            acc.x = fmaf(v.x, wc, acc.x);
            acc.y = fmaf(v.y, wc, acc.y);
            acc.z = fmaf(v.z, wc, acc.z);
            acc.w = fmaf(v.w, wc, acc.w);
        }
        g_part[tid] = acc;
    }
}

// ---------------------------------------------------------------------------
// Kernel 2: combine the 4 chunk partials into g_wimg. 3.9MB traffic, ~1.5us.
// Fixed summation order (chunk 0..3) => deterministic.
// ---------------------------------------------------------------------------
__global__ void __launch_bounds__(256) combine_kernel()
{
    const int per_chunk = NIMG * PIX4;               // 49152 float4s
    int tid = blockIdx.x * blockDim.x + threadIdx.x;
    if (tid >= per_chunk) return;

    float4 a = g_part[tid];
    float4 b = g_part[per_chunk + tid];
    float4 c = g_part[2 * per_chunk + tid];
    float4 d = g_part[3 * per_chunk + tid];
    float4 r;
    r.x = (a.x + b.x) + (c.x + d.x);
    r.y = (a.y + b.y) + (c.y + d.y);
    r.z = (a.z + b.z) + (c.z + d.z);
    r.w = (a.w + b.w) + (c.w + d.w);
    reinterpret_cast<float4*>(g_wimg)[tid] = r;
}

// ---------------------------------------------------------------------------
// Kernel 3: per-point triplane bilinear sample (2 points/thread for ILP).
// ---------------------------------------------------------------------------
__device__ __forceinline__ float bilerp(const float* __restrict__ img,
                                        float u, float v)
{
    float x = u * (float)(RESV - 1);     // align_corners=True unnormalize
    float y = v * (float)(RESV - 1);
    float x0f = floorf(x);
    float y0f = floorf(y);
    float wx = x - x0f;
    float wy = y - y0f;
    int x0 = (int)x0f;
    int y0 = (int)y0f;
    int x1 = min(x0 + 1, RESV - 1);      // u,v in [0,1-1e-5] => x0 in [0,126]
    int y1 = min(y0 + 1, RESV - 1);

    float v00 = __ldg(img + y0 * RESV + x0);
    float v01 = __ldg(img + y0 * RESV + x1);
    float v10 = __ldg(img + y1 * RESV + x0);
    float v11 = __ldg(img + y1 * RESV + x1);

    float iwx = 1.f - wx, iwy = 1.f - wy;
    return v00 * iwx * iwy + v01 * wx * iwy + v10 * iwx * wy + v11 * wx * wy;
}

__device__ __forceinline__ float to_uv(float pc)
{
    const float inv = 1.0f / (1.0f + 0.1f + 1e-5f);   // normalize_coordinate
    float u = pc * inv + 0.5f;
    return fminf(fmaxf(u, 0.0f), 1.0f - 1e-5f);
}

__device__ __forceinline__ float sample_point(
    float px, float py, float pz, int b,
    float w0, float w1, float w2, float bias)
{
    const float* img_xz = g_wimg + (0 * BB + b) * RESV * RESV;
    const float* img_xy = g_wimg + (1 * BB + b) * RESV * RESV;
    const float* img_yz = g_wimg + (2 * BB + b) * RESV * RESV;

    float s = bilerp(img_xz, to_uv(px), to_uv(pz));
    s      += bilerp(img_xy, to_uv(px), to_uv(py));
    s      += bilerp(img_yz, to_uv(py), to_uv(pz));
    return s + px * w0 + py * w1 + pz * w2 + bias;
}

__global__ void __launch_bounds__(256) sample_kernel(
    const float* __restrict__ p,
    const float* __restrict__ fc_w,
    const float* __restrict__ fc_b,
    float* __restrict__ out)
{
    const float w0   = __ldg(fc_w + CC + 0);
    const float w1   = __ldg(fc_w + CC + 1);
    const float w2   = __ldg(fc_w + CC + 2);
    const float bias = __ldg(fc_b);

    int t = blockIdx.x * blockDim.x + threadIdx.x;   // pair index
    int i0 = 2 * t;
    if (i0 >= BB * NN) return;
    // NN even => both points of a pair share the same batch index
    int b = i0 / NN;

    // 6 floats of p for the pair, 8B-aligned (24B * t)
    const float2* pp = reinterpret_cast<const float2*>(p + 3 * i0);
    float2 pa = __ldg(pp + 0);
    float2 pb = __ldg(pp + 1);
    float2 pc = __ldg(pp + 2);

    float r0 = sample_point(pa.x, pa.y, pb.x, b, w0, w1, w2, bias);
    float r1 = sample_point(pb.y, pc.x, pc.y, b, w0, w1, w2, bias);

    reinterpret_cast<float2*>(out + i0)[0] = make_float2(r0, r1);
}

extern "C" void kernel_launch(void* const* d_in, const int* in_sizes, int n_in,
                              void* d_out, int out_size)
{
    const float* p    = (const float*)d_in[0];
    const float* c_xz = (const float*)d_in[1];
    const float* c_xy = (const float*)d_in[2];
    const float* c_yz = (const float*)d_in[3];
    const float* fc_w = (const float*)d_in[4];
    const float* fc_b = (const float*)d_in[5];
    float* out = (float*)d_out;

    // Kernel 1: CHUNKS*12*4096 = 196608 threads -> 768 blocks
    reduce_partial_kernel<<<768, 256>>>(c_xz, c_xy, c_yz, fc_w);

    // Kernel 2: 49152 float4s -> 192 blocks
    combine_kernel<<<192, 256>>>();

    // Kernel 3: 200000 pair-threads -> 782 blocks
    int pairs = (BB * NN) / 2;
    sample_kernel<<<(pairs + 255) / 256, 256>>>(p, fc_w, fc_b, out);
}